// round 5
// baseline (speedup 1.0000x reference)
#include <cuda_runtime.h>

// Problem constants (B=2, S=4096, D=H=512), softmax scale = sqrt(512/8)=8.
#define Bsz 2
#define Sq  4096
#define Dd  512
#define Hh  512

// Scratch (device globals: allocation inside kernel_launch is forbidden).
__device__ float g_q [(size_t)Bsz * Sq * Hh];      // 16 MB  (pre-scaled by 1/8)
__device__ float g_k [(size_t)Bsz * Sq * Hh];      // 16 MB
__device__ float g_v [(size_t)Bsz * Sq * Hh];      // 16 MB
__device__ float g_sc[(size_t)Bsz * Sq * Sq];      // 128 MB (scores -> probs in place)
__device__ float g_at[(size_t)Bsz * Sq * Hh];      // 16 MB

#define BM  128
#define BN  128
#define BKc 8
#define TM  8
#define TN  8
// 256 threads: 16 (tx, cols) x 16 (ty, rows), each owns an 8x8 micro-tile.

// C[M,N] = scale * (A[M,K] @ W[N,K]^T)  (+ bscale * bias[n] if bias != null)
// Optional batch (blockIdx.z) strides; optional skip of blocks strictly below
// the diagonal (used for the anti-causal score GEMM: keep nb >= mb).
__global__ __launch_bounds__(256)
void k_gemm_nt(const float* __restrict__ A, const float* __restrict__ W,
               const float* __restrict__ bias, float* __restrict__ C,
               int M, int N, int K, float scale, float bscale,
               long long sA, long long sW, long long sC, int skip_lower)
{
    int nb = blockIdx.x, mb = blockIdx.y, bz = blockIdx.z;
    if (skip_lower && nb < mb) return;          // block entirely masked (j < i)
    A += (size_t)bz * sA;  W += (size_t)bz * sW;  C += (size_t)bz * sC;

    __shared__ __align__(16) float Ast[BKc][BM + 4];   // [k][m], stride 132
    __shared__ __align__(16) float Bst[BKc][BN + 4];   // [k][n]

    int tid  = threadIdx.x;
    int tx   = tid & 15, ty = tid >> 4;
    int lrow = tid >> 1;                 // 0..127
    int lk4  = (tid & 1) << 2;           // 0 or 4

    const float* Ap = A + (size_t)(mb * BM + lrow) * K + lk4;
    const float* Wp = W + (size_t)(nb * BN + lrow) * K + lk4;

    float acc[TM][TN];
    #pragma unroll
    for (int i = 0; i < TM; i++)
        #pragma unroll
        for (int j = 0; j < TN; j++) acc[i][j] = 0.f;

    for (int kt = 0; kt < K; kt += BKc) {
        float4 av = *(const float4*)(Ap + kt);
        float4 wv = *(const float4*)(Wp + kt);
        Ast[lk4 + 0][lrow] = av.x;  Ast[lk4 + 1][lrow] = av.y;
        Ast[lk4 + 2][lrow] = av.z;  Ast[lk4 + 3][lrow] = av.w;
        Bst[lk4 + 0][lrow] = wv.x;  Bst[lk4 + 1][lrow] = wv.y;
        Bst[lk4 + 2][lrow] = wv.z;  Bst[lk4 + 3][lrow] = wv.w;
        __syncthreads();
        #pragma unroll
        for (int k = 0; k < BKc; k++) {
            float a[TM], b[TN];
            *(float4*)&a[0] = *(const float4*)&Ast[k][ty * TM];
            *(float4*)&a[4] = *(const float4*)&Ast[k][ty * TM + 4];
            *(float4*)&b[0] = *(const float4*)&Bst[k][tx * TN];
            *(float4*)&b[4] = *(const float4*)&Bst[k][tx * TN + 4];
            #pragma unroll
            for (int i = 0; i < TM; i++)
                #pragma unroll
                for (int j = 0; j < TN; j++)
                    acc[i][j] = fmaf(a[i], b[j], acc[i][j]);
        }
        __syncthreads();
    }

    int col0 = nb * BN + tx * TN;
    #pragma unroll
    for (int i = 0; i < TM; i++) {
        int row = mb * BM + ty * TM + i;
        float o[TN];
        #pragma unroll
        for (int j = 0; j < TN; j++) {
            float val = scale * acc[i][j];
            if (bias) val += bscale * bias[col0 + j];
            o[j] = val;
        }
        *(float4*)(C + (size_t)row * N + col0)     = *(float4*)&o[0];
        *(float4*)(C + (size_t)row * N + col0 + 4) = *(float4*)&o[4];
    }
}

// C[M,N] = A[M,K] @ Bm[K,N]   (PV). Per-batch via blockIdx.z. The k-loop starts
// at the row-tile's diagonal (P[i][j] == 0 for j < i; rows of this tile start
// at mb*BM, so all j < mb*BM contribute nothing).
__global__ __launch_bounds__(256)
void k_gemm_nn(const float* __restrict__ A, const float* __restrict__ Bm,
               float* __restrict__ C, int M, int N, int K,
               long long sA, long long sB, long long sC)
{
    int nb = blockIdx.x, mb = blockIdx.y, bz = blockIdx.z;
    A += (size_t)bz * sA;  Bm += (size_t)bz * sB;  C += (size_t)bz * sC;

    __shared__ __align__(16) float Ast[BKc][BM + 4];
    __shared__ __align__(16) float Bst[BKc][BN + 4];

    int tid  = threadIdx.x;
    int tx   = tid & 15, ty = tid >> 4;
    int lrow = tid >> 1;
    int lk4  = (tid & 1) << 2;
    int bk   = tid >> 5;                 // 0..7
    int bn4  = (tid & 31) << 2;          // 0..124

    const float* Ap = A  + (size_t)(mb * BM + lrow) * K + lk4;
    const float* Bp = Bm + (size_t)bk * N + nb * BN + bn4;

    float acc[TM][TN];
    #pragma unroll
    for (int i = 0; i < TM; i++)
        #pragma unroll
        for (int j = 0; j < TN; j++) acc[i][j] = 0.f;

    int kt0 = mb * BM;   // diagonal start (BM-aligned), probs before it are 0
    for (int kt = kt0; kt < K; kt += BKc) {
        float4 av = *(const float4*)(Ap + kt);
        float4 bv = *(const float4*)(Bp + (size_t)kt * N);
        Ast[lk4 + 0][lrow] = av.x;  Ast[lk4 + 1][lrow] = av.y;
        Ast[lk4 + 2][lrow] = av.z;  Ast[lk4 + 3][lrow] = av.w;
        *(float4*)&Bst[bk][bn4] = bv;
        __syncthreads();
        #pragma unroll
        for (int k = 0; k < BKc; k++) {
            float a[TM], b[TN];
            *(float4*)&a[0] = *(const float4*)&Ast[k][ty * TM];
            *(float4*)&a[4] = *(const float4*)&Ast[k][ty * TM + 4];
            *(float4*)&b[0] = *(const float4*)&Bst[k][tx * TN];
            *(float4*)&b[4] = *(const float4*)&Bst[k][tx * TN + 4];
            #pragma unroll
            for (int i = 0; i < TM; i++)
                #pragma unroll
                for (int j = 0; j < TN; j++)
                    acc[i][j] = fmaf(a[i], b[j], acc[i][j]);
        }
        __syncthreads();
    }

    int col0 = nb * BN + tx * TN;
    #pragma unroll
    for (int i = 0; i < TM; i++) {
        int row = mb * BM + ty * TM + i;
        *(float4*)(C + (size_t)row * N + col0)     = *(float4*)&acc[i][0];
        *(float4*)(C + (size_t)row * N + col0 + 4) = *(float4*)&acc[i][4];
    }
}

// Row softmax over the allowed range j in [i, S); zeros written for j < i.
// One CTA per row; in-place on g_sc.
__global__ __launch_bounds__(256)
void k_softmax(float* __restrict__ Sc)
{
    int i = blockIdx.x;
    int b = blockIdx.y;
    float* row = Sc + ((size_t)b * Sq + i) * Sq;
    int t = threadIdx.x;
    __shared__ float red[256];

    // pass 1: max over [i, S)
    float m = -3.402823466e38f;
    for (int j = i + t; j < Sq; j += 256) m = fmaxf(m, row[j]);
    red[t] = m; __syncthreads();
    for (int s = 128; s > 0; s >>= 1) {
        if (t < s) red[t] = fmaxf(red[t], red[t + s]);
        __syncthreads();
    }
    m = red[0];
    __syncthreads();

    // pass 2: sum of exp
    float l = 0.f;
    for (int j = i + t; j < Sq; j += 256) l += __expf(row[j] - m);
    red[t] = l; __syncthreads();
    for (int s = 128; s > 0; s >>= 1) {
        if (t < s) red[t] += red[t + s];
        __syncthreads();
    }
    float inv = 1.0f / red[0];

    // pass 3: write probs; zero the masked prefix (j < i)
    for (int j = t; j < Sq; j += 256) {
        float p = 0.f;
        if (j >= i) p = __expf(row[j] - m) * inv;
        row[j] = p;
    }
}

extern "C" void kernel_launch(void* const* d_in, const int* in_sizes, int n_in,
                              void* d_out, int out_size)
{
    (void)in_sizes; (void)n_in; (void)out_size;
    const float* x  = (const float*)d_in[0];
    const float* Wq = (const float*)d_in[1];
    const float* bq = (const float*)d_in[2];
    const float* Wk = (const float*)d_in[3];
    const float* bk = (const float*)d_in[4];
    const float* Wv = (const float*)d_in[5];
    const float* bv = (const float*)d_in[6];
    const float* Wm = (const float*)d_in[7];
    const float* bm = (const float*)d_in[8];
    float* out = (float*)d_out;

    float *q, *k, *v, *sc, *at;
    cudaGetSymbolAddress((void**)&q,  g_q);
    cudaGetSymbolAddress((void**)&k,  g_k);
    cudaGetSymbolAddress((void**)&v,  g_v);
    cudaGetSymbolAddress((void**)&sc, g_sc);
    cudaGetSymbolAddress((void**)&at, g_at);

    dim3 blk(256);
    dim3 gproj(Hh / BN, (Bsz * Sq) / BM, 1);      // 4 x 64

    // Projections (1/8 softmax scale folded into q, including its bias).
    k_gemm_nt<<<gproj, blk>>>(x, Wq, bq, q, Bsz * Sq, Hh, Dd, 0.125f, 0.125f, 0, 0, 0, 0);
    k_gemm_nt<<<gproj, blk>>>(x, Wk, bk, k, Bsz * Sq, Hh, Dd, 1.0f,   1.0f,   0, 0, 0, 0);
    k_gemm_nt<<<gproj, blk>>>(x, Wv, bv, v, Bsz * Sq, Hh, Dd, 1.0f,   1.0f,   0, 0, 0, 0);

    // Scores: S = q' @ k^T, upper-triangular blocks only (nb >= mb).
    k_gemm_nt<<<dim3(Sq / BN, Sq / BM, Bsz), blk>>>(
        q, k, (const float*)0, sc, Sq, Sq, Hh, 1.0f, 0.0f,
        (long long)Sq * Hh, (long long)Sq * Hh, (long long)Sq * Sq, 1);

    // Row softmax over j >= i (zeros masked prefix).
    k_softmax<<<dim3(Sq, Bsz), blk>>>(sc);

    // attn = P @ v, k-loop starting at the row-tile diagonal.
    k_gemm_nn<<<dim3(Hh / BN, Sq / BM, Bsz), blk>>>(
        sc, v, at, Sq, Hh, Sq,
        (long long)Sq * Sq, (long long)Sq * Hh, (long long)Sq * Hh);

    // out = 8 * attn @ Wm^T + bm  (NUM_HEADS folded into scale).
    k_gemm_nt<<<gproj, blk>>>(at, Wm, bm, out, Bsz * Sq, Hh, Dd, 8.0f, 1.0f, 0, 0, 0, 0);
}

// round 7
// speedup vs baseline: 1.6437x; 1.6437x over previous
#include <cuda_runtime.h>
#include <cstdint>

// Problem constants (B=2, S=4096, D=H=512), softmax scale = sqrt(512/8)=8.
#define Bsz 2
#define Sq  4096
#define Dd  512
#define Hh  512

// Scratch (device globals: allocation inside kernel_launch is forbidden).
__device__ float g_q [(size_t)Bsz * Sq * Hh];      // 16 MB  (pre-scaled by 1/8)
__device__ float g_k [(size_t)Bsz * Sq * Hh];      // 16 MB
__device__ float g_v [(size_t)Bsz * Sq * Hh];      // 16 MB
__device__ float g_vt[(size_t)Bsz * Sq * Hh];      // 16 MB  (v transposed per batch)
__device__ float g_sc[(size_t)Bsz * Sq * Sq];      // 128 MB (scores -> probs in place)
__device__ float g_at[(size_t)Bsz * Sq * Hh];      // 16 MB

// ---------------------------------------------------------------------------
// helpers
// ---------------------------------------------------------------------------
__device__ __forceinline__ uint32_t smem_u32(const void* p) {
    uint32_t a;
    asm("{ .reg .u64 t; cvta.to.shared.u64 t, %1; cvt.u32.u64 %0, t; }"
        : "=r"(a) : "l"(p));
    return a;
}

// fp32 -> nearest tf32 bits (low 13 mantissa bits zeroed, fp32 layout).
__device__ __forceinline__ uint32_t tf32_rna_bits(float x) {
    uint32_t r;
    asm("cvt.rna.tf32.f32 %0, %1;" : "=r"(r) : "f"(x));
    return r;
}

__device__ __forceinline__ void cp16(uint32_t smem, const void* g) {
    asm volatile("cp.async.cg.shared.global [%0], [%1], 16;"
                 :: "r"(smem), "l"(g) : "memory");
}
#define CP_COMMIT() asm volatile("cp.async.commit_group;" ::: "memory")
#define CP_WAIT(n)  asm volatile("cp.async.wait_group %0;" :: "n"(n) : "memory")

// m16n8k8 tf32 mma, D += A*B (row.col; both operands K-major in smem -> NT GEMM)
__device__ __forceinline__ void mma8(float* c, const uint32_t* a, const uint32_t* b) {
    asm volatile(
        "mma.sync.aligned.m16n8k8.row.col.f32.tf32.tf32.f32 "
        "{%0,%1,%2,%3}, {%4,%5,%6,%7}, {%8,%9}, {%0,%1,%2,%3};"
        : "+f"(c[0]), "+f"(c[1]), "+f"(c[2]), "+f"(c[3])
        : "r"(a[0]), "r"(a[1]), "r"(a[2]), "r"(a[3]), "r"(b[0]), "r"(b[1]));
}

// ---------------------------------------------------------------------------
// Tensor-core GEMM (tf32x3 emulated fp32 via mma.sync):
//   C[M,N] = scale * (A[M,K] @ W[N,K]^T)  (+ bscale*bias[n])
// CTA tile 128x128, K-chunk 32. 256 threads = 8 warps (2 M x 4 N), warp tile
// 64x32. fp32 tiles in smem (row stride 36 floats: fragment LDS conflict-free);
// hi/lo tf32 split done in registers. 2-stage cp.async pipeline.
// ---------------------------------------------------------------------------
#define BM 128
#define BN 128
#define KC 32

#define RSTR    36                      // smem row stride in floats
#define TILE_F  (128 * RSTR)            // floats per operand tile
#define B_OFF   (TILE_F * 4)            // byte offset of B tile within stage
#define STAGE_B (2 * TILE_F * 4)        // bytes per stage (A + B)
#define SMEM_SZ (2 * STAGE_B)           // double buffered

__global__ __launch_bounds__(256, 1)
void k_tgemm_nt(const float* __restrict__ A, const float* __restrict__ W,
                const float* __restrict__ bias, float* __restrict__ C,
                int M, int N, int K, float scale, float bscale,
                long long sA, long long sW, long long sC,
                int skip_lower, int diag_kstart)
{
    int nb = blockIdx.x, mb = blockIdx.y, bz = blockIdx.z;
    if (skip_lower && nb < mb) return;          // block entirely masked (j < i)
    A += (size_t)bz * sA;  W += (size_t)bz * sW;  C += (size_t)bz * sC;

    extern __shared__ float smf[];
    uint32_t smb = smem_u32(smf);

    int tid  = threadIdx.x;
    int warp = tid >> 5, lane = tid & 31;
    int wm = warp >> 2, wn = warp & 3;          // warp grid 2 x 4
    int g  = lane >> 2, q4 = lane & 3;          // quad row / k-lane
    int m0 = mb * BM, n0 = nb * BN;

    int kt0 = diag_kstart ? m0 : 0;             // PV: probs zero for k < row tile
    int nch = (K - kt0) / KC;

    float acc[4][4][4];
    #pragma unroll
    for (int i = 0; i < 4; i++)
        #pragma unroll
        for (int j = 0; j < 4; j++)
            #pragma unroll
            for (int r = 0; r < 4; r++) acc[i][j][r] = 0.f;

    // ---- prefetch chunk 0 ----
    {
        int kt = kt0;
        #pragma unroll
        for (int i = 0; i < 4; i++) {
            int idx = tid + i * 256;
            int row = idx >> 3, kq = (idx & 7) << 2;
            cp16(smb + (uint32_t)(row * RSTR + kq) * 4,
                 A + (size_t)(m0 + row) * K + kt + kq);
            cp16(smb + B_OFF + (uint32_t)(row * RSTR + kq) * 4,
                 W + (size_t)(n0 + row) * K + kt + kq);
        }
        CP_COMMIT();
    }

    for (int ic = 0; ic < nch; ic++) {
        // prefetch next chunk into the other stage
        if (ic + 1 < nch) {
            int kt = kt0 + (ic + 1) * KC;
            uint32_t sb = smb + ((ic + 1) & 1) * STAGE_B;
            #pragma unroll
            for (int i = 0; i < 4; i++) {
                int idx = tid + i * 256;
                int row = idx >> 3, kq = (idx & 7) << 2;
                cp16(sb + (uint32_t)(row * RSTR + kq) * 4,
                     A + (size_t)(m0 + row) * K + kt + kq);
                cp16(sb + B_OFF + (uint32_t)(row * RSTR + kq) * 4,
                     W + (size_t)(n0 + row) * K + kt + kq);
            }
            CP_COMMIT();
            CP_WAIT(1);
        } else {
            CP_WAIT(0);
        }
        __syncthreads();

        const float* As = smf + (ic & 1) * (2 * TILE_F);
        const float* Bs = As + TILE_F;

        #pragma unroll
        for (int ks = 0; ks < 4; ks++) {
            int kc = ks * 8 + q4;
            // A fragments for 4 M-tiles, split hi/lo
            uint32_t ah[4][4], al[4][4];
            #pragma unroll
            for (int tm = 0; tm < 4; tm++) {
                int r = wm * 64 + tm * 16 + g;
                float x0 = As[r * RSTR + kc];
                float x1 = As[(r + 8) * RSTR + kc];
                float x2 = As[r * RSTR + kc + 4];
                float x3 = As[(r + 8) * RSTR + kc + 4];
                ah[tm][0] = tf32_rna_bits(x0);
                ah[tm][1] = tf32_rna_bits(x1);
                ah[tm][2] = tf32_rna_bits(x2);
                ah[tm][3] = tf32_rna_bits(x3);
                al[tm][0] = tf32_rna_bits(x0 - __uint_as_float(ah[tm][0]));
                al[tm][1] = tf32_rna_bits(x1 - __uint_as_float(ah[tm][1]));
                al[tm][2] = tf32_rna_bits(x2 - __uint_as_float(ah[tm][2]));
                al[tm][3] = tf32_rna_bits(x3 - __uint_as_float(ah[tm][3]));
            }
            #pragma unroll
            for (int tn = 0; tn < 4; tn++) {
                int n = wn * 32 + tn * 8 + g;
                float y0 = Bs[n * RSTR + kc];
                float y1 = Bs[n * RSTR + kc + 4];
                uint32_t bh[2], bl[2];
                bh[0] = tf32_rna_bits(y0);
                bh[1] = tf32_rna_bits(y1);
                bl[0] = tf32_rna_bits(y0 - __uint_as_float(bh[0]));
                bl[1] = tf32_rna_bits(y1 - __uint_as_float(bh[1]));
                #pragma unroll
                for (int tm = 0; tm < 4; tm++) {
                    mma8(acc[tm][tn], ah[tm], bh);   // hi*hi
                    mma8(acc[tm][tn], ah[tm], bl);   // hi*lo
                    mma8(acc[tm][tn], al[tm], bh);   // lo*hi
                }
            }
        }
        __syncthreads();   // stage reuse barrier (next prefetch overwrites)
    }

    // ---- epilogue ----
    #pragma unroll
    for (int tm = 0; tm < 4; tm++) {
        int r = m0 + wm * 64 + tm * 16 + g;
        #pragma unroll
        for (int tn = 0; tn < 4; tn++) {
            int cc = n0 + wn * 32 + tn * 8 + q4 * 2;
            float bv0 = 0.f, bv1 = 0.f;
            if (bias) {
                bv0 = bscale * __ldg(bias + cc);
                bv1 = bscale * __ldg(bias + cc + 1);
            }
            float2 v0, v1;
            v0.x = scale * acc[tm][tn][0] + bv0;
            v0.y = scale * acc[tm][tn][1] + bv1;
            v1.x = scale * acc[tm][tn][2] + bv0;
            v1.y = scale * acc[tm][tn][3] + bv1;
            *(float2*)(C + (size_t)r * N + cc)       = v0;
            *(float2*)(C + (size_t)(r + 8) * N + cc) = v1;
        }
    }
}

// ---------------------------------------------------------------------------
// Row softmax over the allowed range j in [i, S); zeros written for j < i.
// ---------------------------------------------------------------------------
__global__ __launch_bounds__(256)
void k_softmax(float* __restrict__ Sc)
{
    int i = blockIdx.x;
    int b = blockIdx.y;
    float* row = Sc + ((size_t)b * Sq + i) * Sq;
    int t = threadIdx.x;
    __shared__ float red[256];

    float m = -3.402823466e38f;
    for (int j = i + t; j < Sq; j += 256) m = fmaxf(m, row[j]);
    red[t] = m; __syncthreads();
    for (int s = 128; s > 0; s >>= 1) {
        if (t < s) red[t] = fmaxf(red[t], red[t + s]);
        __syncthreads();
    }
    m = red[0];
    __syncthreads();

    float l = 0.f;
    for (int j = i + t; j < Sq; j += 256) l += __expf(row[j] - m);
    red[t] = l; __syncthreads();
    for (int s = 128; s > 0; s >>= 1) {
        if (t < s) red[t] += red[t + s];
        __syncthreads();
    }
    float inv = 1.0f / red[0];

    for (int j = t; j < Sq; j += 256) {
        float p = 0.f;
        if (j >= i) p = __expf(row[j] - m) * inv;
        row[j] = p;
    }
}

// ---------------------------------------------------------------------------
// Transpose v [S,H] -> vt [H,S], per batch (makes PV an NT GEMM).
// ---------------------------------------------------------------------------
__global__ __launch_bounds__(256)
void k_transpose(const float* __restrict__ V, float* __restrict__ VT)
{
    __shared__ float t[32][33];
    int bz = blockIdx.z;
    const float* Vb = V + (size_t)bz * Sq * Hh;
    float* Tb = VT + (size_t)bz * Sq * Hh;
    int c0 = blockIdx.x * 32, r0 = blockIdx.y * 32;
    int tx = threadIdx.x & 31, ty = threadIdx.x >> 5;  // 8 row-slices
    #pragma unroll
    for (int i = ty; i < 32; i += 8)
        t[i][tx] = Vb[(size_t)(r0 + i) * Hh + c0 + tx];
    __syncthreads();
    #pragma unroll
    for (int i = ty; i < 32; i += 8)
        Tb[(size_t)(c0 + i) * Sq + r0 + tx] = t[tx][i];
}

// ---------------------------------------------------------------------------
extern "C" void kernel_launch(void* const* d_in, const int* in_sizes, int n_in,
                              void* d_out, int out_size)
{
    (void)in_sizes; (void)n_in; (void)out_size;
    const float* x  = (const float*)d_in[0];
    const float* Wq = (const float*)d_in[1];
    const float* bq = (const float*)d_in[2];
    const float* Wk = (const float*)d_in[3];
    const float* bk = (const float*)d_in[4];
    const float* Wv = (const float*)d_in[5];
    const float* bv = (const float*)d_in[6];
    const float* Wm = (const float*)d_in[7];
    const float* bm = (const float*)d_in[8];
    float* out = (float*)d_out;

    float *q, *k, *v, *vt, *sc, *at;
    cudaGetSymbolAddress((void**)&q,  g_q);
    cudaGetSymbolAddress((void**)&k,  g_k);
    cudaGetSymbolAddress((void**)&v,  g_v);
    cudaGetSymbolAddress((void**)&vt, g_vt);
    cudaGetSymbolAddress((void**)&sc, g_sc);
    cudaGetSymbolAddress((void**)&at, g_at);

    cudaFuncSetAttribute(k_tgemm_nt, cudaFuncAttributeMaxDynamicSharedMemorySize, SMEM_SZ);

    dim3 blk(256);
    dim3 gproj(Hh / BN, (Bsz * Sq) / BM, 1);      // 4 x 64

    // Projections (softmax 1/8 folded into q, including its bias).
    k_tgemm_nt<<<gproj, blk, SMEM_SZ>>>(x, Wq, bq, q, Bsz * Sq, Hh, Dd, 0.125f, 0.125f, 0, 0, 0, 0, 0);
    k_tgemm_nt<<<gproj, blk, SMEM_SZ>>>(x, Wk, bk, k, Bsz * Sq, Hh, Dd, 1.0f,   1.0f,   0, 0, 0, 0, 0);
    k_tgemm_nt<<<gproj, blk, SMEM_SZ>>>(x, Wv, bv, v, Bsz * Sq, Hh, Dd, 1.0f,   1.0f,   0, 0, 0, 0, 0);

    // Scores: S = q' @ k^T, upper-triangular blocks only (nb >= mb).
    k_tgemm_nt<<<dim3(Sq / BN, Sq / BM, Bsz), blk, SMEM_SZ>>>(
        q, k, (const float*)0, sc, Sq, Sq, Hh, 1.0f, 0.0f,
        (long long)Sq * Hh, (long long)Sq * Hh, (long long)Sq * Sq, 1, 0);

    // Row softmax over j >= i (zeros masked prefix).
    k_softmax<<<dim3(Sq, Bsz), blk>>>(sc);

    // vt = v^T per batch, then attn = P @ v as NT GEMM with diagonal k-start.
    k_transpose<<<dim3(Hh / 32, Sq / 32, Bsz), blk>>>(v, vt);
    k_tgemm_nt<<<dim3(Hh / BN, Sq / BM, Bsz), blk, SMEM_SZ>>>(
        sc, vt, (const float*)0, at, Sq, Hh, Sq, 1.0f, 0.0f,
        (long long)Sq * Sq, (long long)Sq * Hh, (long long)Sq * Hh, 0, 1);

    // out = 8 * attn @ Wm^T + bm  (NUM_HEADS folded into scale).
    k_tgemm_nt<<<gproj, blk, SMEM_SZ>>>(at, Wm, bm, out, Bsz * Sq, Hh, Dd, 8.0f, 1.0f, 0, 0, 0, 0, 0);
}

// round 8
// speedup vs baseline: 2.8111x; 1.7102x over previous
#include <cuda_runtime.h>
#include <cuda_fp16.h>
#include <cstdint>

// Problem constants (B=2, S=4096, D=H=512), softmax scale = sqrt(512/8)=8.
#define Bsz 2
#define Sq  4096
#define Dd  512
#define Hh  512

// Scratch (device globals: allocation inside kernel_launch is forbidden).
// fp16 hi/lo split pairs for every GEMM operand (fp16x3 fp32 emulation).
__device__ __half g_xh [(size_t)Bsz * Sq * Dd], g_xl [(size_t)Bsz * Sq * Dd];
__device__ __half g_Wqh[Dd * Hh], g_Wql[Dd * Hh];
__device__ __half g_Wkh[Dd * Hh], g_Wkl[Dd * Hh];
__device__ __half g_Wvh[Dd * Hh], g_Wvl[Dd * Hh];
__device__ __half g_Wmh[Hh * Hh], g_Wml[Hh * Hh];
__device__ __half g_qh [(size_t)Bsz * Sq * Hh], g_ql [(size_t)Bsz * Sq * Hh];
__device__ __half g_kh [(size_t)Bsz * Sq * Hh], g_kl [(size_t)Bsz * Sq * Hh];
__device__ float  g_v  [(size_t)Bsz * Sq * Hh];
__device__ __half g_vth[(size_t)Bsz * Sq * Hh], g_vtl[(size_t)Bsz * Sq * Hh];
__device__ float  g_sc [(size_t)Bsz * Sq * Sq];                    // 128 MB
__device__ __half g_ph [(size_t)Bsz * Sq * Sq], g_pl[(size_t)Bsz * Sq * Sq];
__device__ __half g_ath[(size_t)Bsz * Sq * Hh], g_atl[(size_t)Bsz * Sq * Hh];

// ---------------------------------------------------------------------------
// helpers
// ---------------------------------------------------------------------------
__device__ __forceinline__ uint32_t smem_u32(const void* p) {
    uint32_t a;
    asm("{ .reg .u64 t; cvta.to.shared.u64 t, %1; cvt.u32.u64 %0, t; }"
        : "=r"(a) : "l"(p));
    return a;
}
__device__ __forceinline__ void cp16(uint32_t smem, const void* g) {
    asm volatile("cp.async.cg.shared.global [%0], [%1], 16;"
                 :: "r"(smem), "l"(g) : "memory");
}
#define CP_COMMIT() asm volatile("cp.async.commit_group;" ::: "memory")
#define CP_WAIT(n)  asm volatile("cp.async.wait_group %0;" :: "n"(n) : "memory")

// m16n8k16 fp16 mma, fp32 accum. row.col => both operands K-major (NT GEMM).
__device__ __forceinline__ void mma16(float* c, const uint32_t* a, const uint32_t* b) {
    asm volatile(
        "mma.sync.aligned.m16n8k16.row.col.f32.f16.f16.f32 "
        "{%0,%1,%2,%3}, {%4,%5,%6,%7}, {%8,%9}, {%0,%1,%2,%3};"
        : "+f"(c[0]), "+f"(c[1]), "+f"(c[2]), "+f"(c[3])
        : "r"(a[0]), "r"(a[1]), "r"(a[2]), "r"(a[3]), "r"(b[0]), "r"(b[1]));
}

// ---------------------------------------------------------------------------
// fp16x3 GEMM:  C = scale * (A @ W^T) + bscale * bias
// A given as (Ah, Al) fp16 pair, W as (Wh, Wl). Output: fp32 Cf and/or fp16
// pair (Ch, Cl). CTA tile 128x128, K-chunk 64. 512 threads = 16 warps
// (4 M x 4 N), warp tile 32x32. smem row stride 36 b32 -> conflict-free frags.
// ---------------------------------------------------------------------------
#define BM 128
#define BN 128
#define KC 64
#define RS 36                          // b32 per smem row
#define PART (128 * RS)                // 4608 b32 per operand part
#define STAGE (4 * PART)               // Ah | Al | Bh | Bl
#define SMEM_SZ (2 * STAGE * 4)        // bytes, double buffered (144 KB)

__global__ __launch_bounds__(512, 1)
void k_hgemm(const __half* __restrict__ Ah, const __half* __restrict__ Al,
             const __half* __restrict__ Wh, const __half* __restrict__ Wl,
             const float* __restrict__ bias,
             float* __restrict__ Cf, __half* __restrict__ Ch, __half* __restrict__ Cl,
             int M, int N, int K, float scale, float bscale,
             long long sA, long long sW, long long sC,
             int skip_lower, int diag_kstart)
{
    int nb = blockIdx.x, mb = blockIdx.y, bz = blockIdx.z;
    if (skip_lower && nb < mb) return;          // block entirely masked (j < i)
    Ah += (size_t)bz * sA;  Al += (size_t)bz * sA;
    Wh += (size_t)bz * sW;  Wl += (size_t)bz * sW;
    if (Cf) Cf += (size_t)bz * sC;
    if (Ch) { Ch += (size_t)bz * sC; Cl += (size_t)bz * sC; }

    extern __shared__ uint32_t sm32[];
    uint32_t smb = smem_u32(sm32);

    int tid  = threadIdx.x;
    int warp = tid >> 5, lane = tid & 31;
    int wm = warp >> 2, wn = warp & 3;          // warp grid 4 x 4
    int g  = lane >> 2, q4 = lane & 3;
    int m0 = mb * BM, n0 = nb * BN;

    int kt0 = diag_kstart ? m0 : 0;             // PV: probs zero for k < row tile
    int nch = (K - kt0) / KC;

    float acc[2][4][4];
    #pragma unroll
    for (int i = 0; i < 2; i++)
        #pragma unroll
        for (int j = 0; j < 4; j++)
            #pragma unroll
            for (int r = 0; r < 4; r++) acc[i][j][r] = 0.f;

    int lr  = tid >> 3;                         // 0..63
    int seg = tid & 7;                          // 16B segment within 128B row

    // stage loader: 4 parts x 128 rows x 8 segs of 16B = 4096 cp / 512 thr
    auto load_stage = [&](uint32_t sb, int kt) {
        #pragma unroll
        for (int j = 0; j < 2; j++) {
            int row = j * 64 + lr;
            uint32_t so = (uint32_t)(row * RS) * 4 + seg * 16;
            size_t ga = (size_t)(m0 + row) * K + kt + seg * 8;
            size_t gw = (size_t)(n0 + row) * K + kt + seg * 8;
            cp16(sb + so,                 Ah + ga);
            cp16(sb + PART * 4 + so,      Al + ga);
            cp16(sb + 2 * PART * 4 + so,  Wh + gw);
            cp16(sb + 3 * PART * 4 + so,  Wl + gw);
        }
    };

    load_stage(smb, kt0);
    CP_COMMIT();

    for (int ic = 0; ic < nch; ic++) {
        if (ic + 1 < nch) {
            load_stage(smb + ((ic + 1) & 1) * STAGE * 4, kt0 + (ic + 1) * KC);
            CP_COMMIT();
            CP_WAIT(1);
        } else {
            CP_WAIT(0);
        }
        __syncthreads();

        const uint32_t* S0 = sm32 + (ic & 1) * STAGE;
        const uint32_t* Ahs = S0;
        const uint32_t* Als = S0 + PART;
        const uint32_t* Bhs = S0 + 2 * PART;
        const uint32_t* Bls = S0 + 3 * PART;

        #pragma unroll
        for (int ks = 0; ks < 4; ks++) {        // 4 x k16 over KC=64
            int c0 = ks * 8 + q4;
            uint32_t ah[2][4], al[2][4];
            #pragma unroll
            for (int tm = 0; tm < 2; tm++) {
                int r = wm * 32 + tm * 16 + g;
                ah[tm][0] = Ahs[r * RS + c0];
                ah[tm][1] = Ahs[(r + 8) * RS + c0];
                ah[tm][2] = Ahs[r * RS + c0 + 4];
                ah[tm][3] = Ahs[(r + 8) * RS + c0 + 4];
                al[tm][0] = Als[r * RS + c0];
                al[tm][1] = Als[(r + 8) * RS + c0];
                al[tm][2] = Als[r * RS + c0 + 4];
                al[tm][3] = Als[(r + 8) * RS + c0 + 4];
            }
            #pragma unroll
            for (int tn = 0; tn < 4; tn++) {
                int n = wn * 32 + tn * 8 + g;
                uint32_t bh[2], bl[2];
                bh[0] = Bhs[n * RS + c0];
                bh[1] = Bhs[n * RS + c0 + 4];
                bl[0] = Bls[n * RS + c0];
                bl[1] = Bls[n * RS + c0 + 4];
                #pragma unroll
                for (int tm = 0; tm < 2; tm++) {
                    mma16(acc[tm][tn], ah[tm], bh);   // hi*hi
                    mma16(acc[tm][tn], ah[tm], bl);   // hi*lo
                    mma16(acc[tm][tn], al[tm], bh);   // lo*hi
                }
            }
        }
        __syncthreads();   // stage reuse barrier
    }

    // ---- epilogue ----
    #pragma unroll
    for (int tm = 0; tm < 2; tm++) {
        int r = m0 + wm * 32 + tm * 16 + g;
        #pragma unroll
        for (int tn = 0; tn < 4; tn++) {
            int cc = n0 + wn * 32 + tn * 8 + q4 * 2;
            float bv0 = 0.f, bv1 = 0.f;
            if (bias) {
                bv0 = bscale * __ldg(bias + cc);
                bv1 = bscale * __ldg(bias + cc + 1);
            }
            float v00 = scale * acc[tm][tn][0] + bv0;
            float v01 = scale * acc[tm][tn][1] + bv1;
            float v10 = scale * acc[tm][tn][2] + bv0;
            float v11 = scale * acc[tm][tn][3] + bv1;
            if (Cf) {
                *(float2*)(Cf + (size_t)r * N + cc)       = make_float2(v00, v01);
                *(float2*)(Cf + (size_t)(r + 8) * N + cc) = make_float2(v10, v11);
            }
            if (Ch) {
                __half h00 = __float2half_rn(v00), h01 = __float2half_rn(v01);
                __half h10 = __float2half_rn(v10), h11 = __float2half_rn(v11);
                *(__half2*)(Ch + (size_t)r * N + cc)       = __halves2half2(h00, h01);
                *(__half2*)(Ch + (size_t)(r + 8) * N + cc) = __halves2half2(h10, h11);
                *(__half2*)(Cl + (size_t)r * N + cc) = __halves2half2(
                    __float2half_rn(v00 - __half2float(h00)),
                    __float2half_rn(v01 - __half2float(h01)));
                *(__half2*)(Cl + (size_t)(r + 8) * N + cc) = __halves2half2(
                    __float2half_rn(v10 - __half2float(h10)),
                    __float2half_rn(v11 - __half2float(h11)));
            }
        }
    }
}

// ---------------------------------------------------------------------------
// Split fp32 -> fp16 hi/lo pair.
// ---------------------------------------------------------------------------
__global__ __launch_bounds__(256)
void k_split(const float* __restrict__ x, __half* __restrict__ h,
             __half* __restrict__ l, int n)
{
    for (int i = blockIdx.x * 256 + threadIdx.x; i < n; i += gridDim.x * 256) {
        float v = x[i];
        __half hh = __float2half_rn(v);
        h[i] = hh;
        l[i] = __float2half_rn(v - __half2float(hh));
    }
}

// ---------------------------------------------------------------------------
// Row softmax over j in [i, S); writes probs as fp16 hi/lo, zeros for j < i.
// ---------------------------------------------------------------------------
__global__ __launch_bounds__(256)
void k_softmax(const float* __restrict__ Sc, __half* __restrict__ Ph,
               __half* __restrict__ Pl)
{
    int i = blockIdx.x;
    int b = blockIdx.y;
    size_t off = ((size_t)b * Sq + i) * Sq;
    const float* row = Sc + off;
    __half* ph = Ph + off;
    __half* pl = Pl + off;
    int t = threadIdx.x;
    __shared__ float red[256];

    float m = -3.402823466e38f;
    for (int j = i + t; j < Sq; j += 256) m = fmaxf(m, row[j]);
    red[t] = m; __syncthreads();
    for (int s = 128; s > 0; s >>= 1) {
        if (t < s) red[t] = fmaxf(red[t], red[t + s]);
        __syncthreads();
    }
    m = red[0];
    __syncthreads();

    float l = 0.f;
    for (int j = i + t; j < Sq; j += 256) l += __expf(row[j] - m);
    red[t] = l; __syncthreads();
    for (int s = 128; s > 0; s >>= 1) {
        if (t < s) red[t] += red[t + s];
        __syncthreads();
    }
    float inv = 1.0f / red[0];

    for (int j = t; j < Sq; j += 256) {
        float p = 0.f;
        if (j >= i) p = __expf(row[j] - m) * inv;
        __half h = __float2half_rn(p);
        ph[j] = h;
        pl[j] = __float2half_rn(p - __half2float(h));
    }
}

// ---------------------------------------------------------------------------
// Transpose v [S,H] -> vt [H,S] per batch, splitting to fp16 hi/lo.
// ---------------------------------------------------------------------------
__global__ __launch_bounds__(256)
void k_transpose_split(const float* __restrict__ V, __half* __restrict__ Th,
                       __half* __restrict__ Tl)
{
    __shared__ float t[32][33];
    int bz = blockIdx.z;
    const float* Vb = V + (size_t)bz * Sq * Hh;
    __half* Hb = Th + (size_t)bz * Sq * Hh;
    __half* Lb = Tl + (size_t)bz * Sq * Hh;
    int c0 = blockIdx.x * 32, r0 = blockIdx.y * 32;
    int tx = threadIdx.x & 31, ty = threadIdx.x >> 5;
    #pragma unroll
    for (int i = ty; i < 32; i += 8)
        t[i][tx] = Vb[(size_t)(r0 + i) * Hh + c0 + tx];
    __syncthreads();
    #pragma unroll
    for (int i = ty; i < 32; i += 8) {
        float v = t[tx][i];
        __half h = __float2half_rn(v);
        size_t o = (size_t)(c0 + i) * Sq + r0 + tx;
        Hb[o] = h;
        Lb[o] = __float2half_rn(v - __half2float(h));
    }
}

// ---------------------------------------------------------------------------
extern "C" void kernel_launch(void* const* d_in, const int* in_sizes, int n_in,
                              void* d_out, int out_size)
{
    (void)in_sizes; (void)n_in; (void)out_size;
    const float* x  = (const float*)d_in[0];
    const float* Wq = (const float*)d_in[1];
    const float* bq = (const float*)d_in[2];
    const float* Wk = (const float*)d_in[3];
    const float* bk = (const float*)d_in[4];
    const float* Wv = (const float*)d_in[5];
    const float* bv = (const float*)d_in[6];
    const float* Wm = (const float*)d_in[7];
    const float* bm = (const float*)d_in[8];
    float* out = (float*)d_out;

    __half *xh, *xl, *Wqh, *Wql, *Wkh, *Wkl, *Wvh, *Wvl, *Wmh, *Wml;
    __half *qh, *ql, *kh, *kl, *vth, *vtl, *ph, *pl, *ath, *atl;
    float *v, *sc;
    cudaGetSymbolAddress((void**)&xh,  g_xh);  cudaGetSymbolAddress((void**)&xl,  g_xl);
    cudaGetSymbolAddress((void**)&Wqh, g_Wqh); cudaGetSymbolAddress((void**)&Wql, g_Wql);
    cudaGetSymbolAddress((void**)&Wkh, g_Wkh); cudaGetSymbolAddress((void**)&Wkl, g_Wkl);
    cudaGetSymbolAddress((void**)&Wvh, g_Wvh); cudaGetSymbolAddress((void**)&Wvl, g_Wvl);
    cudaGetSymbolAddress((void**)&Wmh, g_Wmh); cudaGetSymbolAddress((void**)&Wml, g_Wml);
    cudaGetSymbolAddress((void**)&qh,  g_qh);  cudaGetSymbolAddress((void**)&ql,  g_ql);
    cudaGetSymbolAddress((void**)&kh,  g_kh);  cudaGetSymbolAddress((void**)&kl,  g_kl);
    cudaGetSymbolAddress((void**)&v,   g_v);
    cudaGetSymbolAddress((void**)&vth, g_vth); cudaGetSymbolAddress((void**)&vtl, g_vtl);
    cudaGetSymbolAddress((void**)&sc,  g_sc);
    cudaGetSymbolAddress((void**)&ph,  g_ph);  cudaGetSymbolAddress((void**)&pl,  g_pl);
    cudaGetSymbolAddress((void**)&ath, g_ath); cudaGetSymbolAddress((void**)&atl, g_atl);

    cudaFuncSetAttribute(k_hgemm, cudaFuncAttributeMaxDynamicSharedMemorySize, SMEM_SZ);

    dim3 blk(512);

    // Split inputs once.
    k_split<<<2048, 256>>>(x,  xh,  xl,  Bsz * Sq * Dd);
    k_split<<<256,  256>>>(Wq, Wqh, Wql, Dd * Hh);
    k_split<<<256,  256>>>(Wk, Wkh, Wkl, Dd * Hh);
    k_split<<<256,  256>>>(Wv, Wvh, Wvl, Dd * Hh);
    k_split<<<256,  256>>>(Wm, Wmh, Wml, Hh * Hh);

    dim3 gproj(Hh / BN, (Bsz * Sq) / BM, 1);      // 4 x 64

    // Projections (softmax 1/8 folded into q, incl. its bias). q,k emitted as
    // fp16 pairs for the score GEMM; v as fp32 for the transpose-split.
    k_hgemm<<<gproj, blk, SMEM_SZ>>>(xh, xl, Wqh, Wql, bq, (float*)0, qh, ql,
                                     Bsz * Sq, Hh, Dd, 0.125f, 0.125f, 0, 0, 0, 0, 0);
    k_hgemm<<<gproj, blk, SMEM_SZ>>>(xh, xl, Wkh, Wkl, bk, (float*)0, kh, kl,
                                     Bsz * Sq, Hh, Dd, 1.0f, 1.0f, 0, 0, 0, 0, 0);
    k_hgemm<<<gproj, blk, SMEM_SZ>>>(xh, xl, Wvh, Wvl, bv, v, (__half*)0, (__half*)0,
                                     Bsz * Sq, Hh, Dd, 1.0f, 1.0f, 0, 0, 0, 0, 0);

    // Scores (fp32), upper-triangular blocks only (nb >= mb).
    k_hgemm<<<dim3(Sq / BN, Sq / BM, Bsz), blk, SMEM_SZ>>>(
        qh, ql, kh, kl, (const float*)0, sc, (__half*)0, (__half*)0,
        Sq, Sq, Hh, 1.0f, 0.0f,
        (long long)Sq * Hh, (long long)Sq * Hh, (long long)Sq * Sq, 1, 0);

    // Row softmax -> probs as fp16 pair (zeros in masked prefix).
    k_softmax<<<dim3(Sq, Bsz), 256>>>(sc, ph, pl);

    // vt = v^T (split), then attn = P @ v as NT GEMM with diagonal k-start.
    k_transpose_split<<<dim3(Hh / 32, Sq / 32, Bsz), 256>>>(v, vth, vtl);
    k_hgemm<<<dim3(Hh / BN, Sq / BM, Bsz), blk, SMEM_SZ>>>(
        ph, pl, vth, vtl, (const float*)0, (float*)0, ath, atl,
        Sq, Hh, Sq, 1.0f, 0.0f,
        (long long)Sq * Sq, (long long)Sq * Hh, (long long)Sq * Hh, 0, 1);

    // out = 8 * attn @ Wm^T + bm  (NUM_HEADS folded into scale).
    k_hgemm<<<gproj, blk, SMEM_SZ>>>(ath, atl, Wmh, Wml, bm, out, (__half*)0, (__half*)0,
                                     Bsz * Sq, Hh, Dd, 8.0f, 1.0f, 0, 0, 0, 0, 0);
}